// round 1
// baseline (speedup 1.0000x reference)
#include <cuda_runtime.h>

// Policy_5480378269890 — NAF policy head, batch=2.
// Single-kernel, single-block (128 threads) implementation. All intermediate
// state lives in shared memory; phases separated by __syncthreads().
//
// Input order (metadata.txt / setup_inputs dict order):
//  0 inputs[2,32] 1 u[2,8]
//  2..5   w1c[16,2,4] b1c[16] w1o[16,48] b1o[16]
//  6..9   w2c b2c w2o b2o
// 10..13  w3c b3c w3o b3o
// 14 g0[32] 15 be0[32]
// 16 W1[128,32] 17 bl1[128] 18 W2[128,128] 19 bl2[128]
// 20 Vw[1,128] 21 Vb[1] 22 Mw[8,128] 23 Mb[8] 24 Lw[64,128] 25 Lb[64]
// Output: mu[2,8] (16) | Q[2,1] (2) | V[2,1] (2)  => 20 floats

struct Params {
    const float* p[26];
    float* out;
};

__device__ __forceinline__ float2 warp_reduce2(float a, float b) {
    #pragma unroll
    for (int off = 16; off > 0; off >>= 1) {
        a += __shfl_xor_sync(0xffffffffu, a, off);
        b += __shfl_xor_sync(0xffffffffu, b, off);
    }
    return make_float2(a, b);
}

__global__ void __launch_bounds__(128, 1) policy_kernel(Params P) {
    __shared__ float pooled[3 * 16 * 3];   // [branch][chan][pool]
    __shared__ float xcat[2][32];
    __shared__ float xbn[2][32];
    __shared__ float h1[2][128];
    __shared__ float h2[2][128];
    __shared__ float Lsm[2][64];
    __shared__ float musm[2][8];
    __shared__ float Vsm[2];

    const int t    = threadIdx.x;
    const int warp = t >> 5;
    const int lane = t & 31;

    const float* inputs = P.p[0];

    // ---------------- Phase 1a: conv1d(2->16,k4,p1) + relu + maxpool2 ----
    if (t < 48) {
        int br = t / 16, o = t % 16;
        const float* wc = P.p[2 + br * 4];
        const float* bc = P.p[3 + br * 4];
        // seg x[i][j] = inputs[i*32 + br*8 + j], i in {0,1}, j in [0,8)
        float y[7];
        #pragma unroll
        for (int tt = 0; tt < 7; tt++) {
            float acc = bc[o];
            #pragma unroll
            for (int i = 0; i < 2; i++) {
                #pragma unroll
                for (int k = 0; k < 4; k++) {
                    int j = tt - 1 + k;
                    if (j >= 0 && j < 8)
                        acc += inputs[i * 32 + br * 8 + j] * wc[o * 8 + i * 4 + k];
                }
            }
            y[tt] = fmaxf(acc, 0.0f);
        }
        #pragma unroll
        for (int s = 0; s < 3; s++)
            pooled[br * 48 + o * 3 + s] = fmaxf(y[2 * s], y[2 * s + 1]);
    }
    __syncthreads();

    // ---------------- Phase 1b: Linear(48,16) per branch, + raw inputs ---
    if (t < 48) {
        int br = t / 16, o = t % 16;
        const float* wo = P.p[4 + br * 4];
        const float* bo = P.p[5 + br * 4];
        float acc = bo[o];
        #pragma unroll 8
        for (int q = 0; q < 48; q++)
            acc += pooled[br * 48 + q] * wo[o * 48 + q];
        // reshape(2,8): row = o/8, col = o%8; column block = br*8
        xcat[o >> 3][br * 8 + (o & 7)] = acc;
    } else if (t < 64) {
        int idx = t - 48, b = idx >> 3, j = idx & 7;
        xcat[b][24 + j] = inputs[b * 32 + 24 + j];
    }
    __syncthreads();

    // ---------------- Phase 2: BatchNorm1d (train mode, batch=2) ---------
    if (t < 32) {
        const float* g  = P.p[14];
        const float* be = P.p[15];
        float x0 = xcat[0][t], x1 = xcat[1][t];
        float m  = 0.5f * (x0 + x1);
        float d0 = x0 - m, d1 = x1 - m;
        float v  = 0.5f * (d0 * d0 + d1 * d1);
        float inv = rsqrtf(v + 1e-5f);
        xbn[0][t] = g[t] * d0 * inv + be[t];
        xbn[1][t] = g[t] * d1 * inv + be[t];
    }
    __syncthreads();

    // ---------------- Phase 3: h1 = tanh(xbn @ W1^T + bl1), K=32 ---------
    {
        const float* W1  = P.p[16];
        const float* bl1 = P.p[17];
        #pragma unroll
        for (int o = warp; o < 128; o += 4) {
            float w  = W1[o * 32 + lane];           // coalesced per warp
            float a0 = w * xbn[0][lane];
            float a1 = w * xbn[1][lane];
            float2 r = warp_reduce2(a0, a1);
            if (lane == 0) {
                h1[0][o] = tanhf(r.x + bl1[o]);
                h1[1][o] = tanhf(r.y + bl1[o]);
            }
        }
    }
    __syncthreads();

    // ---------------- Phase 4: h2 = tanh(h1 @ W2^T + bl2), K=128 ---------
    {
        const float* W2  = P.p[18];
        const float* bl2 = P.p[19];
        #pragma unroll
        for (int o = warp; o < 128; o += 4) {
            float a0 = 0.f, a1 = 0.f;
            #pragma unroll
            for (int k = lane; k < 128; k += 32) {
                float w = W2[o * 128 + k];
                a0 += w * h1[0][k];
                a1 += w * h1[1][k];
            }
            float2 r = warp_reduce2(a0, a1);
            if (lane == 0) {
                h2[0][o] = tanhf(r.x + bl2[o]);
                h2[1][o] = tanhf(r.y + bl2[o]);
            }
        }
    }
    __syncthreads();

    // ---------------- Phase 5: heads (L, mu, V) ---------------------------
    {
        const float* Lw = P.p[24];
        const float* Lb = P.p[25];
        #pragma unroll
        for (int o = warp; o < 64; o += 4) {
            float a0 = 0.f, a1 = 0.f;
            #pragma unroll
            for (int k = lane; k < 128; k += 32) {
                float w = Lw[o * 128 + k];
                a0 += w * h2[0][k];
                a1 += w * h2[1][k];
            }
            float2 r = warp_reduce2(a0, a1);
            if (lane == 0) {
                float p0 = r.x + Lb[o], p1 = r.y + Lb[o];
                int i = o >> 3, j = o & 7;
                Lsm[0][o] = (i > j) ? p0 : ((i == j) ? expf(p0) : 0.0f);
                Lsm[1][o] = (i > j) ? p1 : ((i == j) ? expf(p1) : 0.0f);
            }
        }
        if (warp == 0) {
            const float* Mw = P.p[22];
            const float* Mb = P.p[23];
            #pragma unroll
            for (int o = 0; o < 8; o++) {
                float a0 = 0.f, a1 = 0.f;
                #pragma unroll
                for (int k = lane; k < 128; k += 32) {
                    float w = Mw[o * 128 + k];
                    a0 += w * h2[0][k];
                    a1 += w * h2[1][k];
                }
                float2 r = warp_reduce2(a0, a1);
                if (lane == 0) {
                    musm[0][o] = tanhf(r.x + Mb[o]);
                    musm[1][o] = tanhf(r.y + Mb[o]);
                }
            }
        } else if (warp == 1) {
            const float* Vw = P.p[20];
            const float* Vb = P.p[21];
            float a0 = 0.f, a1 = 0.f;
            #pragma unroll
            for (int k = lane; k < 128; k += 32) {
                float w = Vw[k];
                a0 += w * h2[0][k];
                a1 += w * h2[1][k];
            }
            float2 r = warp_reduce2(a0, a1);
            if (lane == 0) {
                Vsm[0] = r.x + Vb[0];
                Vsm[1] = r.y + Vb[0];
            }
        }
    }
    __syncthreads();

    // ---------------- Phase 6: advantage + outputs -----------------------
    if (t < 16) P.out[t] = musm[t >> 3][t & 7];
    if (t < 2) {
        const float* u = P.p[1];
        float d[8];
        #pragma unroll
        for (int i = 0; i < 8; i++) d[i] = u[t * 8 + i] - musm[t][i];
        // d^T (L L^T) d = || L^T d ||^2
        float acc = 0.f;
        #pragma unroll
        for (int j = 0; j < 8; j++) {
            float y = 0.f;
            #pragma unroll
            for (int i = j; i < 8; i++) y += d[i] * Lsm[t][i * 8 + j];
            acc += y * y;
        }
        P.out[16 + t] = -0.5f * acc + Vsm[t];  // Q
        P.out[18 + t] = Vsm[t];                // V
    }
}

extern "C" void kernel_launch(void* const* d_in, const int* in_sizes, int n_in,
                              void* d_out, int out_size) {
    (void)in_sizes; (void)n_in; (void)out_size;
    Params P;
    #pragma unroll
    for (int i = 0; i < 26; i++) P.p[i] = (const float*)d_in[i];
    P.out = (float*)d_out;
    policy_kernel<<<1, 128>>>(P);
}

// round 2
// speedup vs baseline: 1.5802x; 1.5802x over previous
#include <cuda_runtime.h>

// Policy_5480378269890 — NAF policy head, batch=2.
// Single-kernel, single-block, 512 threads (16 warps). Latency-bound problem:
// minimize the serial dependency chain, not throughput.
//
// Input order:
//  0 inputs[2,32] 1 u[2,8]
//  2..5   w1c[16,2,4] b1c[16] w1o[16,48] b1o[16]
//  6..9   w2c b2c w2o b2o
// 10..13  w3c b3c w3o b3o
// 14 g0[32] 15 be0[32]
// 16 W1[128,32] 17 bl1[128] 18 W2[128,128] 19 bl2[128]
// 20 Vw[1,128] 21 Vb[1] 22 Mw[8,128] 23 Mb[8] 24 Lw[64,128] 25 Lb[64]
// Output: mu[2,8] (16) | Q[2,1] (2) | V[2,1] (2)  => 20 floats

struct Params {
    const float* p[26];
    float* out;
};

__device__ __forceinline__ float2 warp_reduce2(float a, float b) {
    #pragma unroll
    for (int off = 16; off > 0; off >>= 1) {
        a += __shfl_xor_sync(0xffffffffu, a, off);
        b += __shfl_xor_sync(0xffffffffu, b, off);
    }
    return make_float2(a, b);
}

// Branch-free fast tanh: 1 - 2/(exp(2x)+1). __expf is ~2 ulp; robust at +-inf
// (overflow -> inf -> 1, underflow -> 0 -> -1). Abs error ~1e-7.
__device__ __forceinline__ float ftanh(float x) {
    return 1.0f - 2.0f / (__expf(2.0f * x) + 1.0f);
}

__device__ __forceinline__ float dot4(float4 a, float4 b) {
    return a.x * b.x + a.y * b.y + a.z * b.z + a.w * b.w;
}

__global__ void __launch_bounds__(512, 1) policy_kernel(Params P) {
    __shared__ __align__(16) float pooled[3][48];   // [branch][chan*3+pool]
    __shared__ float xcat[2][32];
    __shared__ float xbn[2][32];
    __shared__ __align__(16) float h1[2][128];
    __shared__ __align__(16) float h2[2][128];
    __shared__ float Lsm[2][64];
    __shared__ float musm[2][8];
    __shared__ float Vsm[2];

    const int t    = threadIdx.x;
    const int warp = t >> 5;
    const int lane = t & 31;

    const float* inputs = P.p[0];

    // ---------------- Phase 1a: conv1d(2->16,k4,p1) + relu + maxpool2 ----
    if (t < 48) {
        int br = t / 16, o = t % 16;
        const float* wc = P.p[2 + br * 4];
        const float* bc = P.p[3 + br * 4];
        float y[7];
        #pragma unroll
        for (int tt = 0; tt < 7; tt++) {
            float acc = bc[o];
            #pragma unroll
            for (int i = 0; i < 2; i++) {
                #pragma unroll
                for (int k = 0; k < 4; k++) {
                    int j = tt - 1 + k;
                    if (j >= 0 && j < 8)
                        acc += inputs[i * 32 + br * 8 + j] * wc[o * 8 + i * 4 + k];
                }
            }
            y[tt] = fmaxf(acc, 0.0f);
        }
        #pragma unroll
        for (int s = 0; s < 3; s++)
            pooled[br][o * 3 + s] = fmaxf(y[2 * s], y[2 * s + 1]);
    }
    __syncthreads();

    // ---------------- Phase 1b: Linear(48,16) per branch, + raw inputs ---
    if (t < 48) {
        int br = t / 16, o = t % 16;
        const float* wo = P.p[4 + br * 4];
        const float* bo = P.p[5 + br * 4];
        float acc = bo[o];
        const float4* w4 = reinterpret_cast<const float4*>(wo + o * 48);
        const float4* p4 = reinterpret_cast<const float4*>(&pooled[br][0]);
        #pragma unroll
        for (int q = 0; q < 12; q++)
            acc += dot4(w4[q], p4[q]);
        xcat[o >> 3][br * 8 + (o & 7)] = acc;
    } else if (t < 64) {
        int idx = t - 48, b = idx >> 3, j = idx & 7;
        xcat[b][24 + j] = inputs[b * 32 + 24 + j];
    }
    __syncthreads();

    // ---------------- Phase 2: BatchNorm1d (train mode, batch=2) ---------
    if (t < 32) {
        const float* g  = P.p[14];
        const float* be = P.p[15];
        float x0 = xcat[0][t], x1 = xcat[1][t];
        float m  = 0.5f * (x0 + x1);
        float d0 = x0 - m, d1 = x1 - m;
        float v  = 0.5f * (d0 * d0 + d1 * d1);
        float inv = rsqrtf(v + 1e-5f);
        xbn[0][t] = g[t] * d0 * inv + be[t];
        xbn[1][t] = g[t] * d1 * inv + be[t];
    }
    __syncthreads();

    // ---------------- Phase 3: h1 = tanh(xbn @ W1^T + bl1), K=32 ---------
    {
        const float* W1  = P.p[16];
        const float* bl1 = P.p[17];
        #pragma unroll
        for (int o = warp; o < 128; o += 16) {
            float w  = __ldg(W1 + o * 32 + lane);
            float2 r = warp_reduce2(w * xbn[0][lane], w * xbn[1][lane]);
            if (lane == 0) {
                h1[0][o] = ftanh(r.x + bl1[o]);
                h1[1][o] = ftanh(r.y + bl1[o]);
            }
        }
    }
    __syncthreads();

    // ---------------- Phase 4: h2 = tanh(h1 @ W2^T + bl2), K=128 ---------
    {
        const float* W2  = P.p[18];
        const float* bl2 = P.p[19];
        const float4* x0 = reinterpret_cast<const float4*>(&h1[0][0]);
        const float4* x1 = reinterpret_cast<const float4*>(&h1[1][0]);
        float4 v0 = x0[lane], v1 = x1[lane];
        #pragma unroll
        for (int o = warp; o < 128; o += 16) {
            float4 w = __ldg(reinterpret_cast<const float4*>(W2 + o * 128) + lane);
            float2 r = warp_reduce2(dot4(w, v0), dot4(w, v1));
            if (lane == 0) {
                h2[0][o] = ftanh(r.x + bl2[o]);
                h2[1][o] = ftanh(r.y + bl2[o]);
            }
        }
    }
    __syncthreads();

    // ---------------- Phase 5: unified heads (64 L + 8 mu + 1 V) ---------
    {
        const float* Lw = P.p[24];
        const float* Lb = P.p[25];
        const float* Mw = P.p[22];
        const float* Mb = P.p[23];
        const float* Vw = P.p[20];
        const float* Vb = P.p[21];
        const float4* x0 = reinterpret_cast<const float4*>(&h2[0][0]);
        const float4* x1 = reinterpret_cast<const float4*>(&h2[1][0]);
        float4 v0 = x0[lane], v1 = x1[lane];
        for (int task = warp; task < 73; task += 16) {
            const float* wrow;
            float bias;
            if (task < 64)      { wrow = Lw + task * 128;        bias = Lb[task]; }
            else if (task < 72) { wrow = Mw + (task - 64) * 128; bias = Mb[task - 64]; }
            else                { wrow = Vw;                     bias = Vb[0]; }
            float4 w = __ldg(reinterpret_cast<const float4*>(wrow) + lane);
            float2 r = warp_reduce2(dot4(w, v0), dot4(w, v1));
            if (lane == 0) {
                float p0 = r.x + bias, p1 = r.y + bias;
                if (task < 64) {
                    int i = task >> 3, j = task & 7;
                    Lsm[0][task] = (i > j) ? p0 : ((i == j) ? __expf(p0) : 0.0f);
                    Lsm[1][task] = (i > j) ? p1 : ((i == j) ? __expf(p1) : 0.0f);
                } else if (task < 72) {
                    musm[0][task - 64] = ftanh(p0);
                    musm[1][task - 64] = ftanh(p1);
                } else {
                    Vsm[0] = p0;
                    Vsm[1] = p1;
                }
            }
        }
    }
    __syncthreads();

    // ---------------- Phase 6: advantage + outputs -----------------------
    if (t < 16) P.out[t] = musm[t >> 3][t & 7];
    if (t < 2) {
        const float* u = P.p[1];
        float d[8];
        #pragma unroll
        for (int i = 0; i < 8; i++) d[i] = u[t * 8 + i] - musm[t][i];
        // d^T (L L^T) d = || L^T d ||^2
        float acc = 0.f;
        #pragma unroll
        for (int j = 0; j < 8; j++) {
            float y = 0.f;
            #pragma unroll
            for (int i = j; i < 8; i++) y += d[i] * Lsm[t][i * 8 + j];
            acc += y * y;
        }
        P.out[16 + t] = -0.5f * acc + Vsm[t];  // Q
        P.out[18 + t] = Vsm[t];                // V
    }
}

extern "C" void kernel_launch(void* const* d_in, const int* in_sizes, int n_in,
                              void* d_out, int out_size) {
    (void)in_sizes; (void)n_in; (void)out_size;
    Params P;
    #pragma unroll
    for (int i = 0; i < 26; i++) P.p[i] = (const float*)d_in[i];
    P.out = (float*)d_out;
    policy_kernel<<<1, 512>>>(P);
}

// round 3
// speedup vs baseline: 3.0358x; 1.9211x over previous
#include <cuda_runtime.h>

// Policy_5480378269890 — NAF policy head, batch=2. Single block, 512 threads.
// Latency-bound: all weights prefetched to registers at t=0 (volatile-pinned),
// multi-output butterfly shuffle reductions, prologue confined to warps 14-15.
//
// Inputs: 0 inputs[2,32] 1 u[2,8]
//  2..13 branch params (w*c[16,2,4] b*c[16] w*o[16,48] b*o[16]) x3
//  14 g0[32] 15 be0[32] 16 W1[128,32] 17 bl1[128] 18 W2[128,128] 19 bl2[128]
//  20 Vw[1,128] 21 Vb[1] 22 Mw[8,128] 23 Mb[8] 24 Lw[64,128] 25 Lb[64]
// Output: mu[16] | Q[2] | V[2]

struct Params {
    const float* p[26];
    float* out;
};

__device__ __forceinline__ float4 ldg4v(const float* p) {
    float4 r;
    asm volatile("ld.global.nc.v4.f32 {%0,%1,%2,%3}, [%4];"
                 : "=f"(r.x), "=f"(r.y), "=f"(r.z), "=f"(r.w) : "l"(p));
    return r;
}
__device__ __forceinline__ float ldgv(const float* p) {
    float r;
    asm volatile("ld.global.nc.f32 %0, [%1];" : "=f"(r) : "l"(p));
    return r;
}

__device__ __forceinline__ float dot4(float4 a, float4 b) {
    return a.x * b.x + a.y * b.y + a.z * b.z + a.w * b.w;
}

// Branch-free fast tanh: 1 - 2/(exp(2x)+1), abs err ~1e-7, robust at +-inf.
__device__ __forceinline__ float ftanh(float x) {
    return 1.0f - 2.0f / (__expf(2.0f * x) + 1.0f);
}

// Butterfly-reduce 8 independent per-lane partials (outputs g=0..7) across the
// warp, two batches at once. After return every lane holds the total for
// output g = (lane>>2); lanes with (lane&3)==0 are the canonical writers.
__device__ __forceinline__ float2 bfly8x2(const float p0[8], const float p1[8], int lane) {
    const bool b4 = (lane & 16) != 0;
    const bool b3 = (lane & 8) != 0;
    const bool b2 = (lane & 4) != 0;
    float q0[4], q1[4];
    #pragma unroll
    for (int i = 0; i < 4; i++) {
        float k0 = b4 ? p0[i + 4] : p0[i];
        float s0 = b4 ? p0[i]     : p0[i + 4];
        float k1 = b4 ? p1[i + 4] : p1[i];
        float s1 = b4 ? p1[i]     : p1[i + 4];
        q0[i] = k0 + __shfl_xor_sync(0xffffffffu, s0, 16);
        q1[i] = k1 + __shfl_xor_sync(0xffffffffu, s1, 16);
    }
    float r0[2], r1[2];
    #pragma unroll
    for (int i = 0; i < 2; i++) {
        float k0 = b3 ? q0[i + 2] : q0[i];
        float s0 = b3 ? q0[i]     : q0[i + 2];
        float k1 = b3 ? q1[i + 2] : q1[i];
        float s1 = b3 ? q1[i]     : q1[i + 2];
        r0[i] = k0 + __shfl_xor_sync(0xffffffffu, s0, 8);
        r1[i] = k1 + __shfl_xor_sync(0xffffffffu, s1, 8);
    }
    float k0 = b2 ? r0[1] : r0[0];
    float s0 = b2 ? r0[0] : r0[1];
    float k1 = b2 ? r1[1] : r1[0];
    float s1 = b2 ? r1[0] : r1[1];
    float t0 = k0 + __shfl_xor_sync(0xffffffffu, s0, 4);
    float t1 = k1 + __shfl_xor_sync(0xffffffffu, s1, 4);
    t0 += __shfl_xor_sync(0xffffffffu, t0, 2);
    t1 += __shfl_xor_sync(0xffffffffu, t1, 2);
    t0 += __shfl_xor_sync(0xffffffffu, t0, 1);
    t1 += __shfl_xor_sync(0xffffffffu, t1, 1);
    return make_float2(t0, t1);
}

__global__ void __launch_bounds__(512, 1) policy_kernel(Params P) {
    __shared__ __align__(16) float pooled[3][48];
    __shared__ float xcat[2][32];
    __shared__ float xbn[2][32];
    __shared__ __align__(16) float h1[2][128];
    __shared__ __align__(16) float h2[2][128];
    __shared__ float Lsm[2][64];
    __shared__ float musm[2][8];
    __shared__ float Vsm[2];
    __shared__ float usm[16];

    const int t    = threadIdx.x;
    const int warp = t >> 5;
    const int lane = t & 31;
    const int g    = lane >> 2;            // butterfly output sub-index
    const bool writer = (lane & 3) == 0;

    // ================= t=0 prefetch: pinned-issue weight loads ============
    float  w1r[8];
    float4 w2r[8];
    #pragma unroll
    for (int i = 0; i < 8; i++)
        w1r[i] = ldgv(P.p[16] + (warp * 8 + i) * 32 + lane);
    #pragma unroll
    for (int i = 0; i < 8; i++)
        w2r[i] = ldg4v(P.p[18] + (warp * 8 + i) * 128 + lane * 4);

    float4 whr[8];
    float  hb = 0.0f;
    if (warp < 8) {                         // L head: rows warp*8..warp*8+7
        #pragma unroll
        for (int i = 0; i < 8; i++)
            whr[i] = ldg4v(P.p[24] + (warp * 8 + i) * 128 + lane * 4);
        hb = ldgv(P.p[25] + warp * 8 + g);
    } else if (warp == 8) {                 // mu head
        #pragma unroll
        for (int i = 0; i < 8; i++)
            whr[i] = ldg4v(P.p[22] + i * 128 + lane * 4);
        hb = ldgv(P.p[23] + g);
    } else if (warp == 9) {                 // V head
        whr[0] = ldg4v(P.p[20] + lane * 4);
        hb = ldgv(P.p[21]);
    }
    const float b1r = ldgv(P.p[17] + warp * 8 + g);
    const float b2r = ldgv(P.p[19] + warp * 8 + g);

    // ================= prologue: warps 14-15 only =========================
    if (warp >= 14) {
        const int lt = t - 448;             // 0..63
        const float* inputs = P.p[0];
        if (warp == 15 && lane < 16)
            usm[lane] = ldgv(P.p[1] + lane);

        // Phase 1a: conv1d(2->16,k4,p1) + relu + maxpool2 per branch
        if (lt < 48) {
            int br = lt / 16, o = lt % 16;
            const float* wc = P.p[2 + br * 4];
            const float* bc = P.p[3 + br * 4];
            float y[7];
            #pragma unroll
            for (int tt = 0; tt < 7; tt++) {
                float acc = bc[o];
                #pragma unroll
                for (int i = 0; i < 2; i++) {
                    #pragma unroll
                    for (int k = 0; k < 4; k++) {
                        int j = tt - 1 + k;
                        if (j >= 0 && j < 8)
                            acc += inputs[i * 32 + br * 8 + j] * wc[o * 8 + i * 4 + k];
                    }
                }
                y[tt] = fmaxf(acc, 0.0f);
            }
            #pragma unroll
            for (int s = 0; s < 3; s++)
                pooled[br][o * 3 + s] = fmaxf(y[2 * s], y[2 * s + 1]);
        }
        asm volatile("bar.sync 1, 64;" ::: "memory");

        // Phase 1b: Linear(48,16) + raw passthrough -> xcat
        if (lt < 48) {
            int br = lt / 16, o = lt % 16;
            const float* wo = P.p[4 + br * 4];
            float acc = P.p[5 + br * 4][o];
            const float4* w4 = reinterpret_cast<const float4*>(wo + o * 48);
            const float4* p4 = reinterpret_cast<const float4*>(&pooled[br][0]);
            #pragma unroll
            for (int q = 0; q < 12; q++)
                acc += dot4(w4[q], p4[q]);
            xcat[o >> 3][br * 8 + (o & 7)] = acc;
        } else {
            int idx = lt - 48, b = idx >> 3, j = idx & 7;
            xcat[b][24 + j] = inputs[b * 32 + 24 + j];
        }
        asm volatile("bar.sync 1, 64;" ::: "memory");

        // Phase 2: BatchNorm1d (train mode, batch=2) — warp 14
        if (warp == 14) {
            const float* gg = P.p[14];
            const float* be = P.p[15];
            float x0 = xcat[0][lane], x1 = xcat[1][lane];
            float m  = 0.5f * (x0 + x1);
            float d0 = x0 - m, d1 = x1 - m;
            float v  = 0.5f * (d0 * d0 + d1 * d1);
            float inv = rsqrtf(v + 1e-5f);
            xbn[0][lane] = gg[lane] * d0 * inv + be[lane];
            xbn[1][lane] = gg[lane] * d1 * inv + be[lane];
        }
    }
    __syncthreads();

    // ================= Phase 3: h1 = tanh(xbn @ W1^T + bl1) ===============
    {
        float x0 = xbn[0][lane], x1 = xbn[1][lane];
        float p0[8], p1[8];
        #pragma unroll
        for (int i = 0; i < 8; i++) { p0[i] = w1r[i] * x0; p1[i] = w1r[i] * x1; }
        float2 r = bfly8x2(p0, p1, lane);
        if (writer) {
            int o = warp * 8 + g;
            h1[0][o] = ftanh(r.x + b1r);
            h1[1][o] = ftanh(r.y + b1r);
        }
    }
    __syncthreads();

    // ================= Phase 4: h2 = tanh(h1 @ W2^T + bl2) ================
    {
        float4 v0 = reinterpret_cast<const float4*>(&h1[0][0])[lane];
        float4 v1 = reinterpret_cast<const float4*>(&h1[1][0])[lane];
        float p0[8], p1[8];
        #pragma unroll
        for (int i = 0; i < 8; i++) { p0[i] = dot4(w2r[i], v0); p1[i] = dot4(w2r[i], v1); }
        float2 r = bfly8x2(p0, p1, lane);
        if (writer) {
            int o = warp * 8 + g;
            h2[0][o] = ftanh(r.x + b2r);
            h2[1][o] = ftanh(r.y + b2r);
        }
    }
    __syncthreads();

    // ================= Phase 5: heads (L: warps 0-7, mu: 8, V: 9) =========
    {
        float4 v0 = reinterpret_cast<const float4*>(&h2[0][0])[lane];
        float4 v1 = reinterpret_cast<const float4*>(&h2[1][0])[lane];
        if (warp < 8) {
            float p0[8], p1[8];
            #pragma unroll
            for (int i = 0; i < 8; i++) { p0[i] = dot4(whr[i], v0); p1[i] = dot4(whr[i], v1); }
            float2 r = bfly8x2(p0, p1, lane);
            if (writer) {
                int o = warp * 8 + g;
                int ii = o >> 3, jj = o & 7;
                float pa = r.x + hb, pb = r.y + hb;
                Lsm[0][o] = (ii > jj) ? pa : ((ii == jj) ? __expf(pa) : 0.0f);
                Lsm[1][o] = (ii > jj) ? pb : ((ii == jj) ? __expf(pb) : 0.0f);
            }
        } else if (warp == 8) {
            float p0[8], p1[8];
            #pragma unroll
            for (int i = 0; i < 8; i++) { p0[i] = dot4(whr[i], v0); p1[i] = dot4(whr[i], v1); }
            float2 r = bfly8x2(p0, p1, lane);
            if (writer) {
                musm[0][g] = ftanh(r.x + hb);
                musm[1][g] = ftanh(r.y + hb);
            }
        } else if (warp == 9) {
            float a0 = dot4(whr[0], v0);
            float a1 = dot4(whr[0], v1);
            #pragma unroll
            for (int off = 16; off > 0; off >>= 1) {
                a0 += __shfl_xor_sync(0xffffffffu, a0, off);
                a1 += __shfl_xor_sync(0xffffffffu, a1, off);
            }
            if (lane == 0) { Vsm[0] = a0 + hb; Vsm[1] = a1 + hb; }
        }
    }
    __syncthreads();

    // ================= Phase 6: advantage + outputs (warp 0) ==============
    if (warp == 0) {
        int ln = lane & 15;                 // lanes 16-31 shadow-compute
        int b = ln >> 3, j = ln & 7;
        float d[8];
        #pragma unroll
        for (int i = 0; i < 8; i++) d[i] = usm[b * 8 + i] - musm[b][i];
        float y = 0.0f;
        #pragma unroll
        for (int i = 0; i < 8; i++)
            if (i >= j) y += d[i] * Lsm[b][i * 8 + j];
        float acc = y * y;
        acc += __shfl_xor_sync(0xffffffffu, acc, 1);
        acc += __shfl_xor_sync(0xffffffffu, acc, 2);
        acc += __shfl_xor_sync(0xffffffffu, acc, 4);
        if (lane < 16) {
            P.out[lane] = musm[b][j];                       // mu
            if (j == 0) {
                P.out[16 + b] = -0.5f * acc + Vsm[b];       // Q
                P.out[18 + b] = Vsm[b];                     // V
            }
        }
    }
}

extern "C" void kernel_launch(void* const* d_in, const int* in_sizes, int n_in,
                              void* d_out, int out_size) {
    (void)in_sizes; (void)n_in; (void)out_size;
    Params P;
    #pragma unroll
    for (int i = 0; i < 26; i++) P.p[i] = (const float*)d_in[i];
    P.out = (float*)d_out;
    policy_kernel<<<1, 512>>>(P);
}

// round 4
// speedup vs baseline: 3.1255x; 1.0295x over previous
#include <cuda_runtime.h>

// Policy_5480378269890 — NAF policy head, batch=2. Single block, 512 threads.
// Latency-bound. All weights prefetched to registers at t=0 (pinned LDG order);
// prologue (conv/linear/BN) data staged to smem FIRST by warps 14-15 so its
// loads sit at the front of the single-SM L1tex FIFO; multi-output butterfly
// shuffle reductions.
//
// Inputs: 0 inputs[2,32] 1 u[2,8]
//  2..13 branch params (w*c[16,2,4] b*c[16] w*o[16,48] b*o[16]) x3
//  14 g0[32] 15 be0[32] 16 W1[128,32] 17 bl1[128] 18 W2[128,128] 19 bl2[128]
//  20 Vw[1,128] 21 Vb[1] 22 Mw[8,128] 23 Mb[8] 24 Lw[64,128] 25 Lb[64]
// Output: mu[16] | Q[2] | V[2]

struct Params {
    const float* p[26];
    float* out;
};

__device__ __forceinline__ float4 ldg4v(const float* p) {
    float4 r;
    asm volatile("ld.global.nc.v4.f32 {%0,%1,%2,%3}, [%4];"
                 : "=f"(r.x), "=f"(r.y), "=f"(r.z), "=f"(r.w) : "l"(p));
    return r;
}
__device__ __forceinline__ float ldgv(const float* p) {
    float r;
    asm volatile("ld.global.nc.f32 %0, [%1];" : "=f"(r) : "l"(p));
    return r;
}

__device__ __forceinline__ float dot4(float4 a, float4 b) {
    return a.x * b.x + a.y * b.y + a.z * b.z + a.w * b.w;
}

// Fast tanh: 1 - 2/(exp(2x)+1). __expf + __fdividef, abs err ~1e-6,
// robust at +-inf (exp overflow -> inf -> div 0 -> 1).
__device__ __forceinline__ float ftanh(float x) {
    float e = __expf(2.0f * x);
    return 1.0f - __fdividef(2.0f, e + 1.0f);
}

// Butterfly-reduce 8 independent per-lane partials (outputs g=0..7) across the
// warp, two batches at once. After return lane group g=(lane>>2) holds the
// total for output g; lanes with (lane&3)==0 are canonical writers.
__device__ __forceinline__ float2 bfly8x2(const float p0[8], const float p1[8], int lane) {
    const bool b4 = (lane & 16) != 0;
    const bool b3 = (lane & 8) != 0;
    const bool b2 = (lane & 4) != 0;
    float q0[4], q1[4];
    #pragma unroll
    for (int i = 0; i < 4; i++) {
        float k0 = b4 ? p0[i + 4] : p0[i];
        float s0 = b4 ? p0[i]     : p0[i + 4];
        float k1 = b4 ? p1[i + 4] : p1[i];
        float s1 = b4 ? p1[i]     : p1[i + 4];
        q0[i] = k0 + __shfl_xor_sync(0xffffffffu, s0, 16);
        q1[i] = k1 + __shfl_xor_sync(0xffffffffu, s1, 16);
    }
    float r0[2], r1[2];
    #pragma unroll
    for (int i = 0; i < 2; i++) {
        float k0 = b3 ? q0[i + 2] : q0[i];
        float s0 = b3 ? q0[i]     : q0[i + 2];
        float k1 = b3 ? q1[i + 2] : q1[i];
        float s1 = b3 ? q1[i]     : q1[i + 2];
        r0[i] = k0 + __shfl_xor_sync(0xffffffffu, s0, 8);
        r1[i] = k1 + __shfl_xor_sync(0xffffffffu, s1, 8);
    }
    float k0 = b2 ? r0[1] : r0[0];
    float s0 = b2 ? r0[0] : r0[1];
    float k1 = b2 ? r1[1] : r1[0];
    float s1 = b2 ? r1[0] : r1[1];
    float t0 = k0 + __shfl_xor_sync(0xffffffffu, s0, 4);
    float t1 = k1 + __shfl_xor_sync(0xffffffffu, s1, 4);
    t0 += __shfl_xor_sync(0xffffffffu, t0, 2);
    t1 += __shfl_xor_sync(0xffffffffu, t1, 2);
    t0 += __shfl_xor_sync(0xffffffffu, t0, 1);
    t1 += __shfl_xor_sync(0xffffffffu, t1, 1);
    return make_float2(t0, t1);
}

__global__ void __launch_bounds__(512, 1) policy_kernel(Params P) {
    // Prologue staging (written by warps 14-15 at t=0)
    __shared__ __align__(16) float4 wos[3 * 192];   // wo: 3x16x48 floats
    __shared__ float wcs[3][128];                   // wc: 3x16x8
    __shared__ float bcs[48], bos[48];              // bc, bo
    __shared__ float smem_in[64];                   // inputs[2,32]
    __shared__ float gs[32], bes[32];               // g0, be0
    __shared__ float usm[16];
    // Pipeline state
    __shared__ __align__(16) float pooled[3][48];
    __shared__ float xcat[2][32];
    __shared__ float xbn[2][32];
    __shared__ __align__(16) float h1[2][128];
    __shared__ __align__(16) float h2[2][128];
    __shared__ float Lsm[2][64];
    __shared__ float musm[2][8];
    __shared__ float Vsm[2];

    const int t    = threadIdx.x;
    const int warp = t >> 5;
    const int lane = t & 31;
    const int g    = lane >> 2;
    const bool writer = (lane & 3) == 0;

    float  w1r[8];
    float4 w2r[8];
    float4 whr[8];
    float  hb = 0.0f, b1r, b2r;

    if (warp >= 14) {
        // ============ prologue warps: stage data FIRST (front of FIFO) =====
        const int lt = t - 448;             // 0..63
        smem_in[lt] = ldgv(P.p[0] + lt);
        if (lt < 16) usm[lt] = ldgv(P.p[1] + lt);
        #pragma unroll
        for (int br = 0; br < 3; br++) {
            const float* wo = P.p[4 + br * 4];
            #pragma unroll
            for (int i = 0; i < 3; i++)
                wos[br * 192 + lt + 64 * i] = ldg4v(wo + (lt + 64 * i) * 4);
            const float* wc = P.p[2 + br * 4];
            #pragma unroll
            for (int i = 0; i < 2; i++)
                wcs[br][lt + 64 * i] = ldgv(wc + lt + 64 * i);
        }
        if (lt < 48) {
            bcs[lt] = ldgv(P.p[3 + (lt / 16) * 4] + (lt % 16));
            bos[lt] = ldgv(P.p[5 + (lt / 16) * 4] + (lt % 16));
        }
        if (lt < 32) { gs[lt] = ldgv(P.p[14] + lt); bes[lt] = ldgv(P.p[15] + lt); }

        // then this warp's matvec row prefetch (needed only at phase 3/4)
        #pragma unroll
        for (int i = 0; i < 8; i++)
            w1r[i] = ldgv(P.p[16] + (warp * 8 + i) * 32 + lane);
        #pragma unroll
        for (int i = 0; i < 8; i++)
            w2r[i] = ldg4v(P.p[18] + (warp * 8 + i) * 128 + lane * 4);
        b1r = ldgv(P.p[17] + warp * 8 + g);
        b2r = ldgv(P.p[19] + warp * 8 + g);

        asm volatile("bar.sync 1, 64;" ::: "memory");

        // Phase 1a: conv1d(2->16,k4,p1) + relu + maxpool2 per branch
        if (lt < 48) {
            int br = lt / 16, o = lt % 16;
            float y[7];
            #pragma unroll
            for (int tt = 0; tt < 7; tt++) {
                float acc = bcs[br * 16 + o];
                #pragma unroll
                for (int i = 0; i < 2; i++) {
                    #pragma unroll
                    for (int k = 0; k < 4; k++) {
                        int j = tt - 1 + k;
                        if (j >= 0 && j < 8)
                            acc += smem_in[i * 32 + br * 8 + j] * wcs[br][o * 8 + i * 4 + k];
                    }
                }
                y[tt] = fmaxf(acc, 0.0f);
            }
            #pragma unroll
            for (int s = 0; s < 3; s++)
                pooled[br][o * 3 + s] = fmaxf(y[2 * s], y[2 * s + 1]);
        }
        asm volatile("bar.sync 1, 64;" ::: "memory");

        // Phase 1b: Linear(48,16) + raw passthrough -> xcat
        if (lt < 48) {
            int br = lt / 16, o = lt % 16;
            float acc = bos[br * 16 + o];
            const float4* w4 = &wos[br * 192 + o * 12];
            const float4* p4 = reinterpret_cast<const float4*>(&pooled[br][0]);
            #pragma unroll
            for (int q = 0; q < 12; q++)
                acc += dot4(w4[q], p4[q]);
            xcat[o >> 3][br * 8 + (o & 7)] = acc;
        } else {
            int idx = lt - 48, b = idx >> 3, j = idx & 7;
            xcat[b][24 + j] = smem_in[b * 32 + 24 + j];
        }
        asm volatile("bar.sync 1, 64;" ::: "memory");

        // Phase 2: BatchNorm1d (train, batch=2) — warp 14
        if (warp == 14) {
            float x0 = xcat[0][lane], x1 = xcat[1][lane];
            float m  = 0.5f * (x0 + x1);
            float d0 = x0 - m, d1 = x1 - m;
            float v  = 0.5f * (d0 * d0 + d1 * d1);
            float inv = rsqrtf(v + 1e-5f);
            xbn[0][lane] = gs[lane] * d0 * inv + bes[lane];
            xbn[1][lane] = gs[lane] * d1 * inv + bes[lane];
        }
    } else {
        // ============ compute warps 0-13: weight prefetch only =============
        #pragma unroll
        for (int i = 0; i < 8; i++)
            w1r[i] = ldgv(P.p[16] + (warp * 8 + i) * 32 + lane);
        #pragma unroll
        for (int i = 0; i < 8; i++)
            w2r[i] = ldg4v(P.p[18] + (warp * 8 + i) * 128 + lane * 4);
        if (warp < 8) {                         // L head rows warp*8..+7
            #pragma unroll
            for (int i = 0; i < 8; i++)
                whr[i] = ldg4v(P.p[24] + (warp * 8 + i) * 128 + lane * 4);
            hb = ldgv(P.p[25] + warp * 8 + g);
        } else if (warp == 8) {                 // mu head
            #pragma unroll
            for (int i = 0; i < 8; i++)
                whr[i] = ldg4v(P.p[22] + i * 128 + lane * 4);
            hb = ldgv(P.p[23] + g);
        } else if (warp == 9) {                 // V head
            whr[0] = ldg4v(P.p[20] + lane * 4);
            hb = ldgv(P.p[21]);
        }
        b1r = ldgv(P.p[17] + warp * 8 + g);
        b2r = ldgv(P.p[19] + warp * 8 + g);
    }
    __syncthreads();

    // ================= Phase 3: h1 = tanh(xbn @ W1^T + bl1) ===============
    {
        float x0 = xbn[0][lane], x1 = xbn[1][lane];
        float p0[8], p1[8];
        #pragma unroll
        for (int i = 0; i < 8; i++) { p0[i] = w1r[i] * x0; p1[i] = w1r[i] * x1; }
        float2 r = bfly8x2(p0, p1, lane);
        if (writer) {
            int o = warp * 8 + g;
            h1[0][o] = ftanh(r.x + b1r);
            h1[1][o] = ftanh(r.y + b1r);
        }
    }
    __syncthreads();

    // ================= Phase 4: h2 = tanh(h1 @ W2^T + bl2) ================
    {
        float4 v0 = reinterpret_cast<const float4*>(&h1[0][0])[lane];
        float4 v1 = reinterpret_cast<const float4*>(&h1[1][0])[lane];
        float p0[8], p1[8];
        #pragma unroll
        for (int i = 0; i < 8; i++) { p0[i] = dot4(w2r[i], v0); p1[i] = dot4(w2r[i], v1); }
        float2 r = bfly8x2(p0, p1, lane);
        if (writer) {
            int o = warp * 8 + g;
            h2[0][o] = ftanh(r.x + b2r);
            h2[1][o] = ftanh(r.y + b2r);
        }
    }
    __syncthreads();

    // ================= Phase 5: heads (L: warps 0-7, mu: 8, V: 9) =========
    {
        float4 v0 = reinterpret_cast<const float4*>(&h2[0][0])[lane];
        float4 v1 = reinterpret_cast<const float4*>(&h2[1][0])[lane];
        if (warp < 8) {
            float p0[8], p1[8];
            #pragma unroll
            for (int i = 0; i < 8; i++) { p0[i] = dot4(whr[i], v0); p1[i] = dot4(whr[i], v1); }
            float2 r = bfly8x2(p0, p1, lane);
            if (writer) {
                int o = warp * 8 + g;
                int ii = o >> 3, jj = o & 7;
                float pa = r.x + hb, pb = r.y + hb;
                Lsm[0][o] = (ii > jj) ? pa : ((ii == jj) ? __expf(pa) : 0.0f);
                Lsm[1][o] = (ii > jj) ? pb : ((ii == jj) ? __expf(pb) : 0.0f);
            }
        } else if (warp == 8) {
            float p0[8], p1[8];
            #pragma unroll
            for (int i = 0; i < 8; i++) { p0[i] = dot4(whr[i], v0); p1[i] = dot4(whr[i], v1); }
            float2 r = bfly8x2(p0, p1, lane);
            if (writer) {
                musm[0][g] = ftanh(r.x + hb);
                musm[1][g] = ftanh(r.y + hb);
            }
        } else if (warp == 9) {
            float a0 = dot4(whr[0], v0);
            float a1 = dot4(whr[0], v1);
            #pragma unroll
            for (int off = 16; off > 0; off >>= 1) {
                a0 += __shfl_xor_sync(0xffffffffu, a0, off);
                a1 += __shfl_xor_sync(0xffffffffu, a1, off);
            }
            if (lane == 0) { Vsm[0] = a0 + hb; Vsm[1] = a1 + hb; }
        }
    }
    __syncthreads();

    // ================= Phase 6: advantage + outputs (warp 0) ==============
    if (warp == 0) {
        int ln = lane & 15;
        int b = ln >> 3, j = ln & 7;
        float d[8];
        #pragma unroll
        for (int i = 0; i < 8; i++) d[i] = usm[b * 8 + i] - musm[b][i];
        float y = 0.0f;
        #pragma unroll
        for (int i = 0; i < 8; i++)
            if (i >= j) y += d[i] * Lsm[b][i * 8 + j];
        float acc = y * y;
        acc += __shfl_xor_sync(0xffffffffu, acc, 1);
        acc += __shfl_xor_sync(0xffffffffu, acc, 2);
        acc += __shfl_xor_sync(0xffffffffu, acc, 4);
        if (lane < 16) {
            P.out[lane] = musm[b][j];                       // mu
            if (j == 0) {
                P.out[16 + b] = -0.5f * acc + Vsm[b];       // Q
                P.out[18 + b] = Vsm[b];                     // V
            }
        }
    }
}

extern "C" void kernel_launch(void* const* d_in, const int* in_sizes, int n_in,
                              void* d_out, int out_size) {
    (void)in_sizes; (void)n_in; (void)out_size;
    Params P;
    #pragma unroll
    for (int i = 0; i < 26; i++) P.p[i] = (const float*)d_in[i];
    P.out = (float*)d_out;
    policy_kernel<<<1, 512>>>(P);
}